// round 1
// baseline (speedup 1.0000x reference)
#include <cuda_runtime.h>
#include <cuda_bf16.h>
#include <math.h>

// Problem constants
#define B_   16
#define Hh   8
#define T_   48
#define Np   16
#define C_   512
#define D_   64
#define L_   768           // Np * T_
#define M_   (B_ * L_)     // 12288 rows

// Scratch (global device arrays; no allocation allowed)
__device__ float g_q[(size_t)B_ * Hh * D_ * L_];   // [b][h][d][l']  (t-major l')
__device__ float g_k[(size_t)B_ * Hh * D_ * L_];   // [b][h][d][l']
__device__ float g_v[(size_t)B_ * Hh * L_ * D_];   // [b][h][l'][d]
__device__ float g_y[(size_t)B_ * L_ * C_];        // [b][l][c]  (original l order)

// ---------------------------------------------------------------------------
// Generic 64x64x16 tiled SGEMM: (12288 x 512) @ (512 x 512)
// MODE 0: A = g_y, store plain to Cout (final output)
// MODE 1: A = x,   store Q scaled by 0.125, layout [b][h][d][l'] (t-major)
// MODE 2: A = x,   store K,                 layout [b][h][d][l']
// MODE 3: A = x,   store V,                 layout [b][h][l'][d]
// ---------------------------------------------------------------------------
template <int MODE>
__global__ __launch_bounds__(256) void gemm64(const float* __restrict__ A,
                                              const float* __restrict__ W,
                                              float* __restrict__ Cout) {
    __shared__ float As[16][65];   // [k][m] transposed, padded
    __shared__ float Bs[16][64];   // [k][n]

    const float* Ain = (MODE == 0) ? g_y : A;

    const int m0 = blockIdx.y * 64;
    const int n0 = blockIdx.x * 64;
    const int tid = threadIdx.x;
    const int tx = tid & 15;
    const int ty = tid >> 4;

    const int ar = tid >> 2;           // 0..63
    const int ac = (tid & 3) * 4;      // 0,4,8,12
    const int br = tid >> 4;           // 0..15
    const int bc = (tid & 15) * 4;     // 0..60

    float acc[4][4] = {};

    for (int k0 = 0; k0 < C_; k0 += 16) {
        float4 av = *(const float4*)&Ain[(size_t)(m0 + ar) * C_ + k0 + ac];
        float4 bv = *(const float4*)&W[(size_t)(k0 + br) * C_ + n0 + bc];
        As[ac + 0][ar] = av.x;
        As[ac + 1][ar] = av.y;
        As[ac + 2][ar] = av.z;
        As[ac + 3][ar] = av.w;
        *(float4*)&Bs[br][bc] = bv;
        __syncthreads();
#pragma unroll
        for (int kk = 0; kk < 16; kk++) {
            float a[4], b[4];
#pragma unroll
            for (int i = 0; i < 4; i++) a[i] = As[kk][ty * 4 + i];
#pragma unroll
            for (int j = 0; j < 4; j++) b[j] = Bs[kk][tx * 4 + j];
#pragma unroll
            for (int i = 0; i < 4; i++)
#pragma unroll
                for (int j = 0; j < 4; j++) acc[i][j] += a[i] * b[j];
        }
        __syncthreads();
    }

    const float scale = (MODE == 1) ? 0.125f : 1.0f;  // 1/sqrt(64)

#pragma unroll
    for (int i = 0; i < 4; i++) {
        const int m = m0 + ty * 4 + i;
#pragma unroll
        for (int j = 0; j < 4; j++) {
            const int cc = n0 + tx * 4 + j;
            const float val = acc[i][j] * scale;
            if (MODE == 0) {
                Cout[(size_t)m * C_ + cc] = val;
            } else {
                const int b = m / L_;
                const int l = m - b * L_;
                const int n = l / T_;
                const int t = l - n * T_;
                const int lp = t * Np + n;           // t-major token index
                const int h = cc >> 6;
                const int d = cc & 63;
                if (MODE == 1)
                    g_q[(((size_t)(b * Hh + h)) * D_ + d) * L_ + lp] = val;
                else if (MODE == 2)
                    g_k[(((size_t)(b * Hh + h)) * D_ + d) * L_ + lp] = val;
                else
                    g_v[(((size_t)(b * Hh + h)) * L_ + lp) * D_ + d] = val;
            }
        }
    }
}

// ---------------------------------------------------------------------------
// Flash-style attention with online softmax.
// Grid: (L/64 = 12 q-tiles, B*H = 128). Block: 256 threads (16x16).
// Q,K in [d][l'] (t-major), V in [l'][d]. Causal on t only -> key tiles kt<=qt.
// ---------------------------------------------------------------------------
__global__ __launch_bounds__(256) void attn_kernel(const float* __restrict__ bt_tab,
                                                   const float* __restrict__ bp_tab) {
    __shared__ float Qs[64][64];   // [d][q]
    __shared__ float KPs[64][64];  // phase 1: K [d][k]; phase 2: P [q][k]
    __shared__ float Vs[64][64];   // [k][d]

    const int qt = blockIdx.x;         // 0..11
    const int bh = blockIdx.y;         // 0..127
    const int b = bh >> 3;
    const int h = bh & 7;

    const float* qg = g_q + (size_t)bh * D_ * L_;
    const float* kg = g_k + (size_t)bh * D_ * L_;
    const float* vg = g_v + (size_t)bh * L_ * D_;

    const int tid = threadIdx.x;
    const int tx = tid & 15;
    const int ty = tid >> 4;

    // Load Q tile (64 d-rows x 64 queries)
#pragma unroll
    for (int it = 0; it < 4; it++) {
        const int idx = tid + it * 256;
        const int r = idx >> 4;
        const int c4 = (idx & 15) * 4;
        *(float4*)&Qs[r][c4] = *(const float4*)&qg[(size_t)r * L_ + qt * 64 + c4];
    }

    // This thread's query rows
    int tq[4], nq[4];
#pragma unroll
    for (int i = 0; i < 4; i++) {
        const int lpq = qt * 64 + ty * 4 + i;
        tq[i] = lpq >> 4;   // lp = t*16 + n
        nq[i] = lpq & 15;
    }

    float m_prev[4], ssum[4];
    float o[4][4] = {};
#pragma unroll
    for (int i = 0; i < 4; i++) { m_prev[i] = -1e30f; ssum[i] = 0.0f; }

    __syncthreads();

    for (int kt = 0; kt <= qt; kt++) {
        // Load K tile [d][k] and V tile [k][d]
#pragma unroll
        for (int it = 0; it < 4; it++) {
            const int idx = tid + it * 256;
            const int r = idx >> 4;
            const int c4 = (idx & 15) * 4;
            *(float4*)&KPs[r][c4] = *(const float4*)&kg[(size_t)r * L_ + kt * 64 + c4];
            *(float4*)&Vs[r][c4] = *(const float4*)&vg[(size_t)(kt * 64 + r) * D_ + c4];
        }
        __syncthreads();

        // S = Q^T K  (64q x 64k), 4x4 micro-tile per thread
        float s[4][4] = {};
#pragma unroll
        for (int kk = 0; kk < 64; kk++) {
            float a[4], bb[4];
#pragma unroll
            for (int i = 0; i < 4; i++) a[i] = Qs[kk][ty * 4 + i];
#pragma unroll
            for (int j = 0; j < 4; j++) bb[j] = KPs[kk][tx * 4 + j];
#pragma unroll
            for (int i = 0; i < 4; i++)
#pragma unroll
                for (int j = 0; j < 4; j++) s[i][j] += a[i] * bb[j];
        }

        // Bias + causal mask
#pragma unroll
        for (int j = 0; j < 4; j++) {
            const int lpk = kt * 64 + tx * 4 + j;
            const int tk = lpk >> 4;
            const int nk = lpk & 15;
#pragma unroll
            for (int i = 0; i < 4; i++) {
                if (tk > tq[i]) {
                    s[i][j] = -1e30f;
                } else {
                    s[i][j] += bt_tab[(47 + tk - tq[i]) * Hh + h]
                             + bp_tab[(15 + nk - nq[i]) * Hh + h];
                }
            }
        }

        // Online softmax update (row stats across 16 tx lanes via shfl)
        float alpha[4];
#pragma unroll
        for (int i = 0; i < 4; i++) {
            float mv = fmaxf(fmaxf(s[i][0], s[i][1]), fmaxf(s[i][2], s[i][3]));
#pragma unroll
            for (int off = 8; off >= 1; off >>= 1)
                mv = fmaxf(mv, __shfl_xor_sync(0xffffffffu, mv, off));
            const float mnew = fmaxf(m_prev[i], mv);
            alpha[i] = __expf(m_prev[i] - mnew);
            float rs = 0.0f;
#pragma unroll
            for (int j = 0; j < 4; j++) {
                s[i][j] = __expf(s[i][j] - mnew);
                rs += s[i][j];
            }
#pragma unroll
            for (int off = 8; off >= 1; off >>= 1)
                rs += __shfl_xor_sync(0xffffffffu, rs, off);
            ssum[i] = ssum[i] * alpha[i] + rs;
            m_prev[i] = mnew;
        }
#pragma unroll
        for (int i = 0; i < 4; i++)
#pragma unroll
            for (int j = 0; j < 4; j++) o[i][j] *= alpha[i];

        __syncthreads();   // done reading K from KPs

        // Write P into KPs as [q][k] (contiguous float4 per thread-row)
#pragma unroll
        for (int i = 0; i < 4; i++) {
            float4 pv = make_float4(s[i][0], s[i][1], s[i][2], s[i][3]);
            *(float4*)&KPs[ty * 4 + i][tx * 4] = pv;
        }
        __syncthreads();

        // O += P @ V
#pragma unroll
        for (int kk = 0; kk < 64; kk++) {
            float a[4], bb[4];
#pragma unroll
            for (int i = 0; i < 4; i++) a[i] = KPs[ty * 4 + i][kk];
#pragma unroll
            for (int j = 0; j < 4; j++) bb[j] = Vs[kk][tx * 4 + j];
#pragma unroll
            for (int i = 0; i < 4; i++)
#pragma unroll
                for (int j = 0; j < 4; j++) o[i][j] += a[i] * bb[j];
        }
        __syncthreads();   // before next tile overwrites KPs/Vs
    }

    // Finalize: divide by row sum, write to g_y in ORIGINAL token order
#pragma unroll
    for (int i = 0; i < 4; i++) {
        const float inv = 1.0f / ssum[i];
        const int l = nq[i] * T_ + tq[i];    // back to l = n*T + t
#pragma unroll
        for (int j = 0; j < 4; j++) {
            g_y[((size_t)b * L_ + l) * C_ + h * D_ + tx * 4 + j] = o[i][j] * inv;
        }
    }
}

extern "C" void kernel_launch(void* const* d_in, const int* in_sizes, int n_in,
                              void* d_out, int out_size) {
    const float* x  = (const float*)d_in[0];
    const float* Wq = (const float*)d_in[1];
    const float* Wk = (const float*)d_in[2];
    const float* Wv = (const float*)d_in[3];
    const float* Wo = (const float*)d_in[4];
    const float* bt = (const float*)d_in[5];
    const float* bp = (const float*)d_in[6];
    float* out = (float*)d_out;

    dim3 gg(C_ / 64, M_ / 64);   // (8, 192)

    gemm64<1><<<gg, 256>>>(x, Wq, nullptr);
    gemm64<2><<<gg, 256>>>(x, Wk, nullptr);
    gemm64<3><<<gg, 256>>>(x, Wv, nullptr);
    attn_kernel<<<dim3(L_ / 64, B_ * Hh), 256>>>(bt, bp);
    gemm64<0><<<gg, 256>>>(nullptr, Wo, out);
}

// round 2
// speedup vs baseline: 1.5891x; 1.5891x over previous
#include <cuda_runtime.h>
#include <cuda_bf16.h>
#include <math.h>
#include <stdint.h>

// Problem constants
#define B_   16
#define Hh   8
#define T_   48
#define Np   16
#define C_   512
#define D_   64
#define L_   768           // Np * T_
#define M_   (B_ * L_)     // 12288 rows

// Scratch (global device arrays; no allocation allowed)
__device__ float g_q[(size_t)B_ * Hh * D_ * L_];   // [b][h][d][l']  (t-major l')
__device__ float g_k[(size_t)B_ * Hh * D_ * L_];   // [b][h][d][l']
__device__ float g_v[(size_t)B_ * Hh * L_ * D_];   // [b][h][l'][d]
__device__ float g_y[(size_t)B_ * L_ * C_];        // [b][l][c]  (original l order)

__device__ __forceinline__ uint32_t f2tf(float f) {
    uint32_t u;
    asm("cvt.rna.tf32.f32 %0, %1;" : "=r"(u) : "f"(f));
    return u;
}

__device__ __forceinline__ void mma_tf32(float* d, const uint32_t* a, const uint32_t* b) {
    asm volatile(
        "mma.sync.aligned.m16n8k8.row.col.f32.tf32.tf32.f32 "
        "{%0,%1,%2,%3}, {%4,%5,%6,%7}, {%8,%9}, {%0,%1,%2,%3};"
        : "+f"(d[0]), "+f"(d[1]), "+f"(d[2]), "+f"(d[3])
        : "r"(a[0]), "r"(a[1]), "r"(a[2]), "r"(a[3]), "r"(b[0]), "r"(b[1]));
}

// ---------------------------------------------------------------------------
// Tensor-core tf32 GEMM: (12288 x 512) @ (512 x 512)
// Block 128 threads (4 warps, 2x2 warp grid), block tile 128x128, warp 64x64.
// MODE 0: A = g_y, store plain to Cout (final output)
// MODE 1: A = x,   store Q scaled by 0.125, layout [b][h][d][l'] (t-major)
// MODE 2: A = x,   store K,                 layout [b][h][d][l']
// MODE 3: A = x,   store V,                 layout [b][h][l'][d]
// ---------------------------------------------------------------------------
template <int MODE>
__global__ __launch_bounds__(128) void gemm_tc(const float* __restrict__ A,
                                               const float* __restrict__ W,
                                               float* __restrict__ Cout) {
    __shared__ uint32_t As[128][36];    // [m][k], tf32 bits, padded
    __shared__ uint32_t Bs[32][136];    // [k][n], tf32 bits, padded

    const float* Ain = (MODE == 0) ? g_y : A;

    const int m0 = blockIdx.y * 128;
    const int n0 = blockIdx.x * 128;
    const int tid = threadIdx.x;
    const int lane = tid & 31;
    const int w = tid >> 5;
    const int wr = w & 1;       // warp m-row (0..1)
    const int wc = w >> 1;      // warp n-col (0..1)
    const int r = lane >> 2;    // 0..7
    const int c = lane & 3;     // 0..3

    float acc[4][8][4] = {};

    for (int k0 = 0; k0 < C_; k0 += 32) {
        // Load A tile (128 x 32): 1024 float4-groups... actually 1024 floats*4
#pragma unroll
        for (int f = 0; f < 8; f++) {
            const int idx = tid + f * 128;          // 0..1023
            const int row = idx >> 3;               // 0..127
            const int c4 = (idx & 7) * 4;           // 0..28
            float4 v = *(const float4*)&Ain[(size_t)(m0 + row) * C_ + k0 + c4];
            As[row][c4 + 0] = f2tf(v.x);
            As[row][c4 + 1] = f2tf(v.y);
            As[row][c4 + 2] = f2tf(v.z);
            As[row][c4 + 3] = f2tf(v.w);
        }
        // Load B tile (32 x 128)
#pragma unroll
        for (int f = 0; f < 8; f++) {
            const int idx = tid + f * 128;
            const int row = idx >> 5;               // 0..31
            const int c4 = (idx & 31) * 4;          // 0..124
            float4 v = *(const float4*)&W[(size_t)(k0 + row) * C_ + n0 + c4];
            Bs[row][c4 + 0] = f2tf(v.x);
            Bs[row][c4 + 1] = f2tf(v.y);
            Bs[row][c4 + 2] = f2tf(v.z);
            Bs[row][c4 + 3] = f2tf(v.w);
        }
        __syncthreads();

#pragma unroll
        for (int kk = 0; kk < 32; kk += 8) {
            uint32_t afr[4][4];
#pragma unroll
            for (int mi = 0; mi < 4; mi++) {
                const int mb = wr * 64 + mi * 16;
                afr[mi][0] = As[mb + r][kk + c];
                afr[mi][1] = As[mb + r + 8][kk + c];
                afr[mi][2] = As[mb + r][kk + c + 4];
                afr[mi][3] = As[mb + r + 8][kk + c + 4];
            }
            uint32_t bfr[8][2];
#pragma unroll
            for (int ni = 0; ni < 8; ni++) {
                const int nb = wc * 64 + ni * 8 + r;
                bfr[ni][0] = Bs[kk + c][nb];
                bfr[ni][1] = Bs[kk + c + 4][nb];
            }
#pragma unroll
            for (int mi = 0; mi < 4; mi++)
#pragma unroll
                for (int ni = 0; ni < 8; ni++)
                    mma_tf32(acc[mi][ni], afr[mi], bfr[ni]);
        }
        __syncthreads();
    }

    const float scale = (MODE == 1) ? 0.125f : 1.0f;  // 1/sqrt(64)
    const int c2 = c * 2;

#pragma unroll
    for (int mi = 0; mi < 4; mi++) {
#pragma unroll
        for (int ni = 0; ni < 8; ni++) {
#pragma unroll
            for (int e = 0; e < 4; e++) {
                const int m = m0 + wr * 64 + mi * 16 + r + (e >> 1) * 8;
                const int cc = n0 + wc * 64 + ni * 8 + c2 + (e & 1);
                const float val = acc[mi][ni][e] * scale;
                if (MODE == 0) {
                    Cout[(size_t)m * C_ + cc] = val;
                } else {
                    const int b = m / L_;
                    const int l = m - b * L_;
                    const int n = l / T_;
                    const int t = l - n * T_;
                    const int lp = t * Np + n;           // t-major token index
                    const int h = cc >> 6;
                    const int d = cc & 63;
                    if (MODE == 1)
                        g_q[(((size_t)(b * Hh + h)) * D_ + d) * L_ + lp] = val;
                    else if (MODE == 2)
                        g_k[(((size_t)(b * Hh + h)) * D_ + d) * L_ + lp] = val;
                    else
                        g_v[(((size_t)(b * Hh + h)) * L_ + lp) * D_ + d] = val;
                }
            }
        }
    }
}

// ---------------------------------------------------------------------------
// Flash-style attention with online softmax (fp32 SIMT; unchanged from R1).
// Grid: (L/64 = 12 q-tiles, B*H = 128). Block: 256 threads (16x16).
// Q,K in [d][l'] (t-major), V in [l'][d]. Causal on t only -> key tiles kt<=qt.
// ---------------------------------------------------------------------------
__global__ __launch_bounds__(256) void attn_kernel(const float* __restrict__ bt_tab,
                                                   const float* __restrict__ bp_tab) {
    __shared__ float Qs[64][64];   // [d][q]
    __shared__ float KPs[64][64];  // phase 1: K [d][k]; phase 2: P [q][k]
    __shared__ float Vs[64][64];   // [k][d]

    const int qt = blockIdx.x;         // 0..11
    const int bh = blockIdx.y;         // 0..127
    const int b = bh >> 3;
    const int h = bh & 7;

    const float* qg = g_q + (size_t)bh * D_ * L_;
    const float* kg = g_k + (size_t)bh * D_ * L_;
    const float* vg = g_v + (size_t)bh * L_ * D_;

    const int tid = threadIdx.x;
    const int tx = tid & 15;
    const int ty = tid >> 4;

#pragma unroll
    for (int it = 0; it < 4; it++) {
        const int idx = tid + it * 256;
        const int r = idx >> 4;
        const int c4 = (idx & 15) * 4;
        *(float4*)&Qs[r][c4] = *(const float4*)&qg[(size_t)r * L_ + qt * 64 + c4];
    }

    int tq[4], nq[4];
#pragma unroll
    for (int i = 0; i < 4; i++) {
        const int lpq = qt * 64 + ty * 4 + i;
        tq[i] = lpq >> 4;   // lp = t*16 + n
        nq[i] = lpq & 15;
    }

    float m_prev[4], ssum[4];
    float o[4][4] = {};
#pragma unroll
    for (int i = 0; i < 4; i++) { m_prev[i] = -1e30f; ssum[i] = 0.0f; }

    __syncthreads();

    for (int kt = 0; kt <= qt; kt++) {
#pragma unroll
        for (int it = 0; it < 4; it++) {
            const int idx = tid + it * 256;
            const int r = idx >> 4;
            const int c4 = (idx & 15) * 4;
            *(float4*)&KPs[r][c4] = *(const float4*)&kg[(size_t)r * L_ + kt * 64 + c4];
            *(float4*)&Vs[r][c4] = *(const float4*)&vg[(size_t)(kt * 64 + r) * D_ + c4];
        }
        __syncthreads();

        float s[4][4] = {};
#pragma unroll
        for (int kk = 0; kk < 64; kk++) {
            float a[4], bb[4];
#pragma unroll
            for (int i = 0; i < 4; i++) a[i] = Qs[kk][ty * 4 + i];
#pragma unroll
            for (int j = 0; j < 4; j++) bb[j] = KPs[kk][tx * 4 + j];
#pragma unroll
            for (int i = 0; i < 4; i++)
#pragma unroll
                for (int j = 0; j < 4; j++) s[i][j] += a[i] * bb[j];
        }

#pragma unroll
        for (int j = 0; j < 4; j++) {
            const int lpk = kt * 64 + tx * 4 + j;
            const int tk = lpk >> 4;
            const int nk = lpk & 15;
#pragma unroll
            for (int i = 0; i < 4; i++) {
                if (tk > tq[i]) {
                    s[i][j] = -1e30f;
                } else {
                    s[i][j] += bt_tab[(47 + tk - tq[i]) * Hh + h]
                             + bp_tab[(15 + nk - nq[i]) * Hh + h];
                }
            }
        }

        float alpha[4];
#pragma unroll
        for (int i = 0; i < 4; i++) {
            float mv = fmaxf(fmaxf(s[i][0], s[i][1]), fmaxf(s[i][2], s[i][3]));
#pragma unroll
            for (int off = 8; off >= 1; off >>= 1)
                mv = fmaxf(mv, __shfl_xor_sync(0xffffffffu, mv, off));
            const float mnew = fmaxf(m_prev[i], mv);
            alpha[i] = __expf(m_prev[i] - mnew);
            float rs = 0.0f;
#pragma unroll
            for (int j = 0; j < 4; j++) {
                s[i][j] = __expf(s[i][j] - mnew);
                rs += s[i][j];
            }
#pragma unroll
            for (int off = 8; off >= 1; off >>= 1)
                rs += __shfl_xor_sync(0xffffffffu, rs, off);
            ssum[i] = ssum[i] * alpha[i] + rs;
            m_prev[i] = mnew;
        }
#pragma unroll
        for (int i = 0; i < 4; i++)
#pragma unroll
            for (int j = 0; j < 4; j++) o[i][j] *= alpha[i];

        __syncthreads();

#pragma unroll
        for (int i = 0; i < 4; i++) {
            float4 pv = make_float4(s[i][0], s[i][1], s[i][2], s[i][3]);
            *(float4*)&KPs[ty * 4 + i][tx * 4] = pv;
        }
        __syncthreads();

#pragma unroll
        for (int kk = 0; kk < 64; kk++) {
            float a[4], bb[4];
#pragma unroll
            for (int i = 0; i < 4; i++) a[i] = KPs[ty * 4 + i][kk];
#pragma unroll
            for (int j = 0; j < 4; j++) bb[j] = Vs[kk][tx * 4 + j];
#pragma unroll
            for (int i = 0; i < 4; i++)
#pragma unroll
                for (int j = 0; j < 4; j++) o[i][j] += a[i] * bb[j];
        }
        __syncthreads();
    }

#pragma unroll
    for (int i = 0; i < 4; i++) {
        const float inv = 1.0f / ssum[i];
        const int l = nq[i] * T_ + tq[i];    // back to l = n*T + t
#pragma unroll
        for (int j = 0; j < 4; j++) {
            g_y[((size_t)b * L_ + l) * C_ + h * D_ + tx * 4 + j] = o[i][j] * inv;
        }
    }
}

extern "C" void kernel_launch(void* const* d_in, const int* in_sizes, int n_in,
                              void* d_out, int out_size) {
    const float* x  = (const float*)d_in[0];
    const float* Wq = (const float*)d_in[1];
    const float* Wk = (const float*)d_in[2];
    const float* Wv = (const float*)d_in[3];
    const float* Wo = (const float*)d_in[4];
    const float* bt = (const float*)d_in[5];
    const float* bp = (const float*)d_in[6];
    float* out = (float*)d_out;

    dim3 gg(C_ / 128, M_ / 128);   // (4, 96)

    gemm_tc<1><<<gg, 128>>>(x, Wq, nullptr);
    gemm_tc<2><<<gg, 128>>>(x, Wk, nullptr);
    gemm_tc<3><<<gg, 128>>>(x, Wv, nullptr);
    attn_kernel<<<dim3(L_ / 64, B_ * Hh), 256>>>(bt, bp);
    gemm_tc<0><<<gg, 128>>>(nullptr, Wo, out);
}

// round 3
// speedup vs baseline: 2.0716x; 1.3036x over previous
#include <cuda_runtime.h>
#include <cuda_bf16.h>
#include <math.h>
#include <stdint.h>

// Problem constants
#define B_   16
#define Hh   8
#define T_   48
#define Np   16
#define C_   512
#define D_   64
#define L_   768           // Np * T_
#define M_   (B_ * L_)     // 12288 rows

// Scratch (global device arrays; no allocation allowed)
__device__ float g_q[(size_t)B_ * Hh * D_ * L_];   // [b][h][d][l']  (t-major l')
__device__ float g_k[(size_t)B_ * Hh * D_ * L_];   // [b][h][d][l']
__device__ float g_v[(size_t)B_ * Hh * L_ * D_];   // [b][h][l'][d]
__device__ float g_y[(size_t)B_ * L_ * C_];        // [b][l][c]  (original l order)

__device__ __forceinline__ uint32_t f2tf(float f) {
    uint32_t u;
    asm("cvt.rna.tf32.f32 %0, %1;" : "=r"(u) : "f"(f));
    return u;
}

__device__ __forceinline__ void mma_tf32(float* d, const uint32_t* a, const uint32_t* b) {
    asm volatile(
        "mma.sync.aligned.m16n8k8.row.col.f32.tf32.tf32.f32 "
        "{%0,%1,%2,%3}, {%4,%5,%6,%7}, {%8,%9}, {%0,%1,%2,%3};"
        : "+f"(d[0]), "+f"(d[1]), "+f"(d[2]), "+f"(d[3])
        : "r"(a[0]), "r"(a[1]), "r"(a[2]), "r"(a[3]), "r"(b[0]), "r"(b[1]));
}

// ---------------------------------------------------------------------------
// Tensor-core tf32 GEMM: (12288 x 512) @ (512 x 512)  (unchanged from R2)
// ---------------------------------------------------------------------------
template <int MODE>
__global__ __launch_bounds__(128) void gemm_tc(const float* __restrict__ A,
                                               const float* __restrict__ W,
                                               float* __restrict__ Cout) {
    __shared__ uint32_t As[128][36];    // [m][k], tf32 bits, padded
    __shared__ uint32_t Bs[32][136];    // [k][n], tf32 bits, padded

    const float* Ain = (MODE == 0) ? g_y : A;

    const int m0 = blockIdx.y * 128;
    const int n0 = blockIdx.x * 128;
    const int tid = threadIdx.x;
    const int lane = tid & 31;
    const int w = tid >> 5;
    const int wr = w & 1;
    const int wc = w >> 1;
    const int r = lane >> 2;
    const int c = lane & 3;

    float acc[4][8][4] = {};

    for (int k0 = 0; k0 < C_; k0 += 32) {
#pragma unroll
        for (int f = 0; f < 8; f++) {
            const int idx = tid + f * 128;
            const int row = idx >> 3;
            const int c4 = (idx & 7) * 4;
            float4 v = *(const float4*)&Ain[(size_t)(m0 + row) * C_ + k0 + c4];
            As[row][c4 + 0] = f2tf(v.x);
            As[row][c4 + 1] = f2tf(v.y);
            As[row][c4 + 2] = f2tf(v.z);
            As[row][c4 + 3] = f2tf(v.w);
        }
#pragma unroll
        for (int f = 0; f < 8; f++) {
            const int idx = tid + f * 128;
            const int row = idx >> 5;
            const int c4 = (idx & 31) * 4;
            float4 v = *(const float4*)&W[(size_t)(k0 + row) * C_ + n0 + c4];
            Bs[row][c4 + 0] = f2tf(v.x);
            Bs[row][c4 + 1] = f2tf(v.y);
            Bs[row][c4 + 2] = f2tf(v.z);
            Bs[row][c4 + 3] = f2tf(v.w);
        }
        __syncthreads();

#pragma unroll
        for (int kk = 0; kk < 32; kk += 8) {
            uint32_t afr[4][4];
#pragma unroll
            for (int mi = 0; mi < 4; mi++) {
                const int mb = wr * 64 + mi * 16;
                afr[mi][0] = As[mb + r][kk + c];
                afr[mi][1] = As[mb + r + 8][kk + c];
                afr[mi][2] = As[mb + r][kk + c + 4];
                afr[mi][3] = As[mb + r + 8][kk + c + 4];
            }
            uint32_t bfr[8][2];
#pragma unroll
            for (int ni = 0; ni < 8; ni++) {
                const int nb = wc * 64 + ni * 8 + r;
                bfr[ni][0] = Bs[kk + c][nb];
                bfr[ni][1] = Bs[kk + c + 4][nb];
            }
#pragma unroll
            for (int mi = 0; mi < 4; mi++)
#pragma unroll
                for (int ni = 0; ni < 8; ni++)
                    mma_tf32(acc[mi][ni], afr[mi], bfr[ni]);
        }
        __syncthreads();
    }

    const float scale = (MODE == 1) ? 0.125f : 1.0f;
    const int c2 = c * 2;

#pragma unroll
    for (int mi = 0; mi < 4; mi++) {
#pragma unroll
        for (int ni = 0; ni < 8; ni++) {
#pragma unroll
            for (int e = 0; e < 4; e++) {
                const int m = m0 + wr * 64 + mi * 16 + r + (e >> 1) * 8;
                const int cc = n0 + wc * 64 + ni * 8 + c2 + (e & 1);
                const float val = acc[mi][ni][e] * scale;
                if (MODE == 0) {
                    Cout[(size_t)m * C_ + cc] = val;
                } else {
                    const int b = m / L_;
                    const int l = m - b * L_;
                    const int n = l / T_;
                    const int t = l - n * T_;
                    const int lp = t * Np + n;
                    const int h = cc >> 6;
                    const int d = cc & 63;
                    if (MODE == 1)
                        g_q[(((size_t)(b * Hh + h)) * D_ + d) * L_ + lp] = val;
                    else if (MODE == 2)
                        g_k[(((size_t)(b * Hh + h)) * D_ + d) * L_ + lp] = val;
                    else
                        g_v[(((size_t)(b * Hh + h)) * L_ + lp) * D_ + d] = val;
                }
            }
        }
    }
}

// ---------------------------------------------------------------------------
// Tensor-core flash attention, tf32 mma for S=QK^T and O=PV.
// Grid: (12 q-tiles, 128 bh). Block: 128 threads (4 warps).
// Each warp owns 16 query rows. Q fragments live in registers.
// K staged in smem (tf32 bits), buffer reused for P. V staged in smem.
// Causal on t only; mask needed only on diagonal tile (t-major packing).
// ---------------------------------------------------------------------------
__global__ __launch_bounds__(128) void attn_tc(const float* __restrict__ bt_tab,
                                               const float* __restrict__ bp_tab) {
    __shared__ uint32_t KPs[64][68];   // K tile [d][k], then P tile [q][k]
    __shared__ uint32_t Vs[64][68];    // V tile [k][d]
    __shared__ float bt_s[95];
    __shared__ float bp_s[31];

    const int qt = 11 - blockIdx.x;    // long blocks first
    const int bh = blockIdx.y;
    const int b = bh >> 3;
    const int h = bh & 7;

    const float* qg = g_q + (size_t)bh * D_ * L_;
    const float* kg = g_k + (size_t)bh * D_ * L_;
    const float* vg = g_v + (size_t)bh * L_ * D_;

    const int tid = threadIdx.x;
    const int lane = tid & 31;
    const int w = tid >> 5;
    const int r = lane >> 2;   // 0..7
    const int c = lane & 3;    // 0..3

    if (tid < 95) bt_s[tid] = bt_tab[tid * Hh + h];
    if (tid < 31) bp_s[tid] = bp_tab[tid * Hh + h];

    const int row0 = qt * 64 + w * 16 + r;   // global lp (t-major) of row0
    const int row1 = row0 + 8;
    const int tq0 = row0 >> 4, nq0 = row0 & 15;
    const int tq1 = row1 >> 4, nq1 = row1 & 15;

    // Q fragments (A operand, rows row0/row1, k = d dimension)
    uint32_t qf[8][4];
#pragma unroll
    for (int ks = 0; ks < 8; ks++) {
        const int d0 = ks * 8 + c;
        qf[ks][0] = f2tf(qg[(size_t)d0 * L_ + row0]);
        qf[ks][1] = f2tf(qg[(size_t)d0 * L_ + row1]);
        qf[ks][2] = f2tf(qg[(size_t)(d0 + 4) * L_ + row0]);
        qf[ks][3] = f2tf(qg[(size_t)(d0 + 4) * L_ + row1]);
    }

    float m0 = -1e30f, m1 = -1e30f;
    float l0 = 0.0f, l1 = 0.0f;
    float o[8][4] = {};

    __syncthreads();   // bias tables visible

    for (int kt = 0; kt <= qt; kt++) {
        // Load K [d][k] and V [k][d] tiles, converting to tf32 bits
#pragma unroll
        for (int it = 0; it < 4; it++) {
            const int idx = tid + it * 128;        // 0..511
            const int rr = idx >> 3;               // 0..63
            const int c8 = (idx & 7) * 8;          // 0..56
            float4 ka = *(const float4*)&kg[(size_t)rr * L_ + kt * 64 + c8];
            float4 kb = *(const float4*)&kg[(size_t)rr * L_ + kt * 64 + c8 + 4];
            float4 va = *(const float4*)&vg[(size_t)(kt * 64 + rr) * D_ + c8];
            float4 vb = *(const float4*)&vg[(size_t)(kt * 64 + rr) * D_ + c8 + 4];
            uint4 ku = make_uint4(f2tf(ka.x), f2tf(ka.y), f2tf(ka.z), f2tf(ka.w));
            uint4 ku2 = make_uint4(f2tf(kb.x), f2tf(kb.y), f2tf(kb.z), f2tf(kb.w));
            uint4 vu = make_uint4(f2tf(va.x), f2tf(va.y), f2tf(va.z), f2tf(va.w));
            uint4 vu2 = make_uint4(f2tf(vb.x), f2tf(vb.y), f2tf(vb.z), f2tf(vb.w));
            *(uint4*)&KPs[rr][c8] = ku;
            *(uint4*)&KPs[rr][c8 + 4] = ku2;
            *(uint4*)&Vs[rr][c8] = vu;
            *(uint4*)&Vs[rr][c8 + 4] = vu2;
        }
        __syncthreads();

        // S = Q K  (16q x 64k per warp)
        float s[8][4] = {};
#pragma unroll
        for (int ks = 0; ks < 8; ks++) {
            const int d0 = ks * 8 + c;
#pragma unroll
            for (int ni = 0; ni < 8; ni++) {
                uint32_t bfr[2];
                bfr[0] = KPs[d0][ni * 8 + r];
                bfr[1] = KPs[d0 + 4][ni * 8 + r];
                mma_tf32(s[ni], qf[ks], bfr);
            }
        }

        // Bias + causal mask (mask only on diagonal tile)
        const bool diag = (kt == qt);
#pragma unroll
        for (int ni = 0; ni < 8; ni++) {
#pragma unroll
            for (int e = 0; e < 4; e++) {
                const int col = ni * 8 + c * 2 + (e & 1);
                const int lpk = kt * 64 + col;
                const int tk = lpk >> 4;
                const int nk = lpk & 15;
                const int tq = (e < 2) ? tq0 : tq1;
                const int nq = (e < 2) ? nq0 : nq1;
                s[ni][e] += bt_s[47 + tk - tq] + bp_s[15 + nk - nq];
                if (diag && tk > tq) s[ni][e] = -1e30f;
            }
        }

        // Online softmax (rows split over lane quads: reduce over c via xor 1,2)
        float mx0 = -1e30f, mx1 = -1e30f;
#pragma unroll
        for (int ni = 0; ni < 8; ni++) {
            mx0 = fmaxf(mx0, fmaxf(s[ni][0], s[ni][1]));
            mx1 = fmaxf(mx1, fmaxf(s[ni][2], s[ni][3]));
        }
        mx0 = fmaxf(mx0, __shfl_xor_sync(0xffffffffu, mx0, 1));
        mx0 = fmaxf(mx0, __shfl_xor_sync(0xffffffffu, mx0, 2));
        mx1 = fmaxf(mx1, __shfl_xor_sync(0xffffffffu, mx1, 1));
        mx1 = fmaxf(mx1, __shfl_xor_sync(0xffffffffu, mx1, 2));

        const float mn0 = fmaxf(m0, mx0);
        const float mn1 = fmaxf(m1, mx1);
        const float a0 = __expf(m0 - mn0);
        const float a1 = __expf(m1 - mn1);

        float rs0 = 0.0f, rs1 = 0.0f;
#pragma unroll
        for (int ni = 0; ni < 8; ni++) {
            s[ni][0] = __expf(s[ni][0] - mn0);
            s[ni][1] = __expf(s[ni][1] - mn0);
            s[ni][2] = __expf(s[ni][2] - mn1);
            s[ni][3] = __expf(s[ni][3] - mn1);
            rs0 += s[ni][0] + s[ni][1];
            rs1 += s[ni][2] + s[ni][3];
        }
        rs0 += __shfl_xor_sync(0xffffffffu, rs0, 1);
        rs0 += __shfl_xor_sync(0xffffffffu, rs0, 2);
        rs1 += __shfl_xor_sync(0xffffffffu, rs1, 1);
        rs1 += __shfl_xor_sync(0xffffffffu, rs1, 2);

        l0 = l0 * a0 + rs0;
        l1 = l1 * a1 + rs1;
        m0 = mn0;
        m1 = mn1;

#pragma unroll
        for (int ni = 0; ni < 8; ni++) {
            o[ni][0] *= a0; o[ni][1] *= a0;
            o[ni][2] *= a1; o[ni][3] *= a1;
        }

        __syncthreads();   // all warps done reading K before P overwrites it

        // Store P into KPs as [q][k] (tf32 bits). Warp-local rows.
        const int pr0 = w * 16 + r;
#pragma unroll
        for (int ni = 0; ni < 8; ni++) {
            const int col = ni * 8 + c * 2;
            *(uint2*)&KPs[pr0][col] = make_uint2(f2tf(s[ni][0]), f2tf(s[ni][1]));
            *(uint2*)&KPs[pr0 + 8][col] = make_uint2(f2tf(s[ni][2]), f2tf(s[ni][3]));
        }
        __syncwarp();

        // O += P @ V  (k = key dim, 8 steps)
#pragma unroll
        for (int ks = 0; ks < 8; ks++) {
            const int k0 = ks * 8 + c;
            uint32_t af[4];
            af[0] = KPs[pr0][k0];
            af[1] = KPs[pr0 + 8][k0];
            af[2] = KPs[pr0][k0 + 4];
            af[3] = KPs[pr0 + 8][k0 + 4];
#pragma unroll
            for (int ni = 0; ni < 8; ni++) {
                uint32_t bfr[2];
                bfr[0] = Vs[k0][ni * 8 + r];
                bfr[1] = Vs[k0 + 4][ni * 8 + r];
                mma_tf32(o[ni], af, bfr);
            }
        }
        __syncthreads();   // before next tile overwrites KPs/Vs
    }

    // Finalize and write to g_y in ORIGINAL token order
    const float i0 = 1.0f / l0;
    const float i1 = 1.0f / l1;
    const int lq0 = nq0 * T_ + tq0;
    const int lq1 = nq1 * T_ + tq1;
    float* y0 = &g_y[((size_t)b * L_ + lq0) * C_ + h * D_];
    float* y1 = &g_y[((size_t)b * L_ + lq1) * C_ + h * D_];
#pragma unroll
    for (int ni = 0; ni < 8; ni++) {
        const int col = ni * 8 + c * 2;
        *(float2*)&y0[col] = make_float2(o[ni][0] * i0, o[ni][1] * i0);
        *(float2*)&y1[col] = make_float2(o[ni][2] * i1, o[ni][3] * i1);
    }
}

extern "C" void kernel_launch(void* const* d_in, const int* in_sizes, int n_in,
                              void* d_out, int out_size) {
    const float* x  = (const float*)d_in[0];
    const float* Wq = (const float*)d_in[1];
    const float* Wk = (const float*)d_in[2];
    const float* Wv = (const float*)d_in[3];
    const float* Wo = (const float*)d_in[4];
    const float* bt = (const float*)d_in[5];
    const float* bp = (const float*)d_in[6];
    float* out = (float*)d_out;

    dim3 gg(C_ / 128, M_ / 128);   // (4, 96)

    gemm_tc<1><<<gg, 128>>>(x, Wq, nullptr);
    gemm_tc<2><<<gg, 128>>>(x, Wk, nullptr);
    gemm_tc<3><<<gg, 128>>>(x, Wv, nullptr);
    attn_tc<<<dim3(L_ / 64, B_ * Hh), 128>>>(bt, bp);
    gemm_tc<0><<<gg, 128>>>(nullptr, Wo, out);
}

// round 4
// speedup vs baseline: 3.2560x; 1.5717x over previous
#include <cuda_runtime.h>
#include <cuda_bf16.h>
#include <math.h>
#include <stdint.h>

// Problem constants
#define B_   16
#define Hh   8
#define T_   48
#define Np   16
#define C_   512
#define D_   64
#define L_   768           // Np * T_
#define M_   (B_ * L_)     // 12288 rows

// Scratch (global device arrays; no allocation allowed)
__device__ float g_q[(size_t)B_ * Hh * D_ * L_];   // [b][h][d][l']  (t-major l')
__device__ float g_k[(size_t)B_ * Hh * D_ * L_];   // [b][h][d][l']
__device__ float g_v[(size_t)B_ * Hh * L_ * D_];   // [b][h][l'][d]
__device__ float g_y[(size_t)B_ * L_ * C_];        // [b][l][c]  (original l order)

__device__ __forceinline__ uint32_t f2tf(float f) {
    uint32_t u;
    asm("cvt.rna.tf32.f32 %0, %1;" : "=r"(u) : "f"(f));
    return u;
}

__device__ __forceinline__ void mma_tf32(float* d, const uint32_t* a, const uint32_t* b) {
    asm volatile(
        "mma.sync.aligned.m16n8k8.row.col.f32.tf32.tf32.f32 "
        "{%0,%1,%2,%3}, {%4,%5,%6,%7}, {%8,%9}, {%0,%1,%2,%3};"
        : "+f"(d[0]), "+f"(d[1]), "+f"(d[2]), "+f"(d[3])
        : "r"(a[0]), "r"(a[1]), "r"(a[2]), "r"(a[3]), "r"(b[0]), "r"(b[1]));
}

// ---------------------------------------------------------------------------
// Pipelined tensor-core tf32 GEMM.
// MODE 0: out = g_y @ W0               grid (4, 96)
// MODE 1: fused QKV: x @ {Wq,Wk,Wv}    grid (12, 96), wsel = n0g>>9
// Block 128 threads (4 warps 2x2), block tile 128x128, K-step 32, 16 iters.
// A stored in fragment-native smem layout (uint4 operand loads).
// B stored plain [k][n] padded (conflict-free scalar operand loads, uint4 STS).
// ---------------------------------------------------------------------------
template <int MODE>
__global__ __launch_bounds__(128) void gemm_tc(const float* __restrict__ X,
                                               const float* __restrict__ W0,
                                               const float* __restrict__ W1,
                                               const float* __restrict__ W2,
                                               float* __restrict__ Cout) {
    __shared__ uint32_t Asf[8 * 4 * 132];   // frag layout: [m_tile][k_step] chunks of 132
    __shared__ uint32_t Bsf[32 * 136];      // plain [k][n], pad 136

    const float* Ain = (MODE == 0) ? g_y : X;
    const int n0g = blockIdx.x * 128;
    const float* W;
    int wsel = 0;
    if (MODE == 1) {
        wsel = n0g >> 9;
        W = (wsel == 0) ? W0 : (wsel == 1) ? W1 : W2;
    } else {
        W = W0;
    }
    const int n0 = (MODE == 1) ? (n0g & 511) : n0g;
    const int m0 = blockIdx.y * 128;

    const int tid = threadIdx.x;
    const int lane = tid & 31;
    const int w = tid >> 5;
    const int wr = w & 1;
    const int wc = w >> 1;
    const int r = lane >> 2;
    const int c = lane & 3;

    float acc[4][8][4] = {};

    // A-load mapping: row = f*16 + s, cols (tid&7)*4 .. +3
    const int s_a = tid >> 3;           // 0..15
    const int c4_a = (tid & 7) * 4;     // 0..28
    // B-load mapping: krow = f*4 + (tid>>5), cols (tid&31)*4 .. +3
    const int kr_b = tid >> 5;          // 0..3
    const int u_b = tid & 31;

    float4 aR[8], bR[8];
#pragma unroll
    for (int f = 0; f < 8; f++) {
        aR[f] = *(const float4*)&Ain[(size_t)(m0 + f * 16 + s_a) * C_ + c4_a];
        bR[f] = *(const float4*)&W[(size_t)(f * 4 + kr_b) * C_ + n0 + u_b * 4];
    }

    // A STS target pieces
    const int a_chunk = ((tid & 7) >> 1);          // k_step
    const int a_val = (s_a >> 3) + 2 * (tid & 1);  // half_m + 2*half_k
    const int a_lanebase = (s_a & 7) * 16;         // (row&7)*4 words *4

    for (int k0 = 0; k0 < C_; k0 += 32) {
        // STS phase (from prefetch regs)
#pragma unroll
        for (int f = 0; f < 8; f++) {
            const float av[4] = {aR[f].x, aR[f].y, aR[f].z, aR[f].w};
            const int abase = (f * 4 + a_chunk) * 132 + a_lanebase + a_val;
#pragma unroll
            for (int j = 0; j < 4; j++) Asf[abase + j * 4] = f2tf(av[j]);
            uint4 bv = make_uint4(f2tf(bR[f].x), f2tf(bR[f].y), f2tf(bR[f].z), f2tf(bR[f].w));
            *(uint4*)&Bsf[(f * 4 + kr_b) * 136 + u_b * 4] = bv;
        }
        __syncthreads();

        if (k0 + 32 < C_) {
            const int k1 = k0 + 32;
#pragma unroll
            for (int f = 0; f < 8; f++) {
                aR[f] = *(const float4*)&Ain[(size_t)(m0 + f * 16 + s_a) * C_ + k1 + c4_a];
                bR[f] = *(const float4*)&W[(size_t)(k1 + f * 4 + kr_b) * C_ + n0 + u_b * 4];
            }
        }

        // compute 4 k-steps of 8
#pragma unroll
        for (int ks = 0; ks < 4; ks++) {
            uint4 afr[4];
#pragma unroll
            for (int mi = 0; mi < 4; mi++)
                afr[mi] = *(const uint4*)&Asf[((wr * 4 + mi) * 4 + ks) * 132 + lane * 4];
            uint32_t bfr[8][2];
            const int kc = ks * 8 + c;
#pragma unroll
            for (int ni = 0; ni < 8; ni++) {
                const int nb = wc * 64 + ni * 8 + r;
                bfr[ni][0] = Bsf[kc * 136 + nb];
                bfr[ni][1] = Bsf[(kc + 4) * 136 + nb];
            }
#pragma unroll
            for (int mi = 0; mi < 4; mi++)
#pragma unroll
                for (int ni = 0; ni < 8; ni++)
                    mma_tf32(acc[mi][ni], (const uint32_t*)&afr[mi], bfr[ni]);
        }
        __syncthreads();
    }

    const float scale = (MODE == 1 && wsel == 0) ? 0.125f : 1.0f;
    const int c2 = c * 2;

#pragma unroll
    for (int mi = 0; mi < 4; mi++) {
#pragma unroll
        for (int ni = 0; ni < 8; ni++) {
#pragma unroll
            for (int e = 0; e < 4; e++) {
                const int m = m0 + wr * 64 + mi * 16 + r + (e >> 1) * 8;
                const int cc = n0 + wc * 64 + ni * 8 + c2 + (e & 1);
                const float val = acc[mi][ni][e] * scale;
                if (MODE == 0) {
                    Cout[(size_t)m * C_ + cc] = val;
                } else {
                    const int b = m / L_;
                    const int l = m - b * L_;
                    const int n = l / T_;
                    const int t = l - n * T_;
                    const int lp = t * Np + n;
                    const int h = cc >> 6;
                    const int d = cc & 63;
                    if (wsel == 0)
                        g_q[(((size_t)(b * Hh + h)) * D_ + d) * L_ + lp] = val;
                    else if (wsel == 1)
                        g_k[(((size_t)(b * Hh + h)) * D_ + d) * L_ + lp] = val;
                    else
                        g_v[(((size_t)(b * Hh + h)) * L_ + lp) * D_ + d] = val;
                }
            }
        }
    }
}

// ---------------------------------------------------------------------------
// Tensor-core flash attention. Fragment-native smem layouts for K/V/P with
// XOR bank swizzles; K/V global loads pipelined through registers.
// Grid: (12 q-tiles, 128 bh). Block: 128 threads (4 warps, 16 q-rows each).
// ---------------------------------------------------------------------------
__global__ __launch_bounds__(128) void attn_tc(const float* __restrict__ bt_tab,
                                               const float* __restrict__ bp_tab) {
    __shared__ uint32_t KPs[4096];   // K-frag [ni][ks][..]; later P-frag [w][ks][..]
    __shared__ uint32_t Vs[4096];    // V-frag [ni][ks][..]
    __shared__ float bt_s[95];
    __shared__ float bp_s[31];

    const int qt = 11 - blockIdx.x;    // long blocks first
    const int bh = blockIdx.y;
    const int b = bh >> 3;
    const int h = bh & 7;

    const float* qg = g_q + (size_t)bh * D_ * L_;
    const float* kg = g_k + (size_t)bh * D_ * L_;
    const float* vg = g_v + (size_t)bh * L_ * D_;

    const int tid = threadIdx.x;
    const int lane = tid & 31;
    const int w = tid >> 5;
    const int r = lane >> 2;   // 0..7
    const int c = lane & 3;    // 0..3

    if (tid < 95) bt_s[tid] = bt_tab[tid * Hh + h];
    if (tid < 31) bp_s[tid] = bp_tab[tid * Hh + h];

    const int row0 = qt * 64 + w * 16 + r;
    const int row1 = row0 + 8;
    const int tq0 = row0 >> 4, nq0 = row0 & 15;
    const int tq1 = row1 >> 4, nq1 = row1 & 15;

    // Q fragments (A operand, rows row0/row1, k = d dimension)
    uint32_t qf[8][4];
#pragma unroll
    for (int ks = 0; ks < 8; ks++) {
        const int d0 = ks * 8 + c;
        qf[ks][0] = f2tf(qg[(size_t)d0 * L_ + row0]);
        qf[ks][1] = f2tf(qg[(size_t)d0 * L_ + row1]);
        qf[ks][2] = f2tf(qg[(size_t)(d0 + 4) * L_ + row0]);
        qf[ks][3] = f2tf(qg[(size_t)(d0 + 4) * L_ + row1]);
    }

    // loader-thread constants
    const int ld_s = tid >> 3;          // 0..15
    const int ld_ni = tid & 7;          // key/d column group
    const int ld_c8 = ld_ni * 8;
    const int ld_xor = 8 * (ld_ni & 3);

    float m0 = -1e30f, m1 = -1e30f;
    float l0 = 0.0f, l1 = 0.0f;
    float o[8][4] = {};

    // prefetch kt=0 tiles
    float4 kR[8], vR[8];
#pragma unroll
    for (int it = 0; it < 4; it++) {
        const int rr = it * 16 + ld_s;
        kR[it * 2]     = *(const float4*)&kg[(size_t)rr * L_ + ld_c8];
        kR[it * 2 + 1] = *(const float4*)&kg[(size_t)rr * L_ + ld_c8 + 4];
        vR[it * 2]     = *(const float4*)&vg[(size_t)rr * D_ + ld_c8];
        vR[it * 2 + 1] = *(const float4*)&vg[(size_t)rr * D_ + ld_c8 + 4];
    }

    __syncthreads();   // bias tables visible

    const uint32_t pSwz = (uint32_t)(lane * 4) ^ ((uint32_t)(r & 7) << 2);
    const uint32_t kSwz = (uint32_t)(lane * 2);

    for (int kt = 0; kt <= qt; kt++) {
        // STS K/V fragments from prefetch regs
#pragma unroll
        for (int it = 0; it < 4; it++) {
            const int rr = it * 16 + ld_s;
            const int ks = rr >> 3;
            const int dc = rr & 7;
            const int cc2 = (dc & 3) * 2;
            const int val = dc >> 2;
            const int kbase = (ld_ni * 8 + ks) * 64 + val;
            const float kv[8] = {kR[it*2].x, kR[it*2].y, kR[it*2].z, kR[it*2].w,
                                 kR[it*2+1].x, kR[it*2+1].y, kR[it*2+1].z, kR[it*2+1].w};
            const float vv[8] = {vR[it*2].x, vR[it*2].y, vR[it*2].z, vR[it*2].w,
                                 vR[it*2+1].x, vR[it*2+1].y, vR[it*2+1].z, vR[it*2+1].w};
#pragma unroll
            for (int j = 0; j < 8; j++) {
                const int off = ((8 * j + cc2) ^ ld_xor);
                KPs[kbase + off] = f2tf(kv[j]);
                Vs[kbase + off] = f2tf(vv[j]);
            }
        }
        __syncthreads();

        // prefetch next tile
        if (kt < qt) {
            const int kn = (kt + 1) * 64;
#pragma unroll
            for (int it = 0; it < 4; it++) {
                const int rr = it * 16 + ld_s;
                kR[it * 2]     = *(const float4*)&kg[(size_t)rr * L_ + kn + ld_c8];
                kR[it * 2 + 1] = *(const float4*)&kg[(size_t)rr * L_ + kn + ld_c8 + 4];
                vR[it * 2]     = *(const float4*)&vg[(size_t)(kn + rr) * D_ + ld_c8];
                vR[it * 2 + 1] = *(const float4*)&vg[(size_t)(kn + rr) * D_ + ld_c8 + 4];
            }
        }

        // S = Q K  (16q x 64k per warp)
        float s[8][4] = {};
#pragma unroll
        for (int ks = 0; ks < 8; ks++) {
#pragma unroll
            for (int ni = 0; ni < 8; ni++) {
                uint2 bf = *(const uint2*)&KPs[(ni * 8 + ks) * 64 + (kSwz ^ (8 * (ni & 3)))];
                mma_tf32(s[ni], qf[ks], (const uint32_t*)&bf);
            }
        }

        // Bias + causal mask (mask only on diagonal tile)
        const bool diag = (kt == qt);
#pragma unroll
        for (int ni = 0; ni < 8; ni++) {
#pragma unroll
            for (int e = 0; e < 4; e++) {
                const int col = ni * 8 + c * 2 + (e & 1);
                const int lpk = kt * 64 + col;
                const int tk = lpk >> 4;
                const int nk = lpk & 15;
                const int tq = (e < 2) ? tq0 : tq1;
                const int nq = (e < 2) ? nq0 : nq1;
                s[ni][e] += bt_s[47 + tk - tq] + bp_s[15 + nk - nq];
                if (diag && tk > tq) s[ni][e] = -1e30f;
            }
        }

        // Online softmax (reduce over lane quads via xor 1,2)
        float mx0 = -1e30f, mx1 = -1e30f;
#pragma unroll
        for (int ni = 0; ni < 8; ni++) {
            mx0 = fmaxf(mx0, fmaxf(s[ni][0], s[ni][1]));
            mx1 = fmaxf(mx1, fmaxf(s[ni][2], s[ni][3]));
        }
        mx0 = fmaxf(mx0, __shfl_xor_sync(0xffffffffu, mx0, 1));
        mx0 = fmaxf(mx0, __shfl_xor_sync(0xffffffffu, mx0, 2));
        mx1 = fmaxf(mx1, __shfl_xor_sync(0xffffffffu, mx1, 1));
        mx1 = fmaxf(mx1, __shfl_xor_sync(0xffffffffu, mx1, 2));

        const float mn0 = fmaxf(m0, mx0);
        const float mn1 = fmaxf(m1, mx1);
        const float a0 = __expf(m0 - mn0);
        const float a1 = __expf(m1 - mn1);

        float rs0 = 0.0f, rs1 = 0.0f;
#pragma unroll
        for (int ni = 0; ni < 8; ni++) {
            s[ni][0] = __expf(s[ni][0] - mn0);
            s[ni][1] = __expf(s[ni][1] - mn0);
            s[ni][2] = __expf(s[ni][2] - mn1);
            s[ni][3] = __expf(s[ni][3] - mn1);
            rs0 += s[ni][0] + s[ni][1];
            rs1 += s[ni][2] + s[ni][3];
        }
        rs0 += __shfl_xor_sync(0xffffffffu, rs0, 1);
        rs0 += __shfl_xor_sync(0xffffffffu, rs0, 2);
        rs1 += __shfl_xor_sync(0xffffffffu, rs1, 1);
        rs1 += __shfl_xor_sync(0xffffffffu, rs1, 2);

        l0 = l0 * a0 + rs0;
        l1 = l1 * a1 + rs1;
        m0 = mn0;
        m1 = mn1;

#pragma unroll
        for (int ni = 0; ni < 8; ni++) {
            o[ni][0] *= a0; o[ni][1] *= a0;
            o[ni][2] *= a1; o[ni][3] *= a1;
        }

        __syncthreads();   // all warps done reading K-frag before P overwrites

        // Store P fragments (warp-local region of KPs)
#pragma unroll
        for (int ni = 0; ni < 8; ni++) {
#pragma unroll
            for (int e = 0; e < 4; e++) {
                const int kc = 2 * c + (e & 1);
                const int c_t = kc & 3;
                const int half_k = kc >> 2;
                const uint32_t lane_t = (uint32_t)(r * 4 + c_t);
                const int val = (e >> 1) + 2 * half_k;
                const uint32_t word = (uint32_t)((w * 8 + ni) * 128)
                                    + ((lane_t * 4) ^ (((lane_t >> 2) & 7) << 2)) + val;
                KPs[word] = f2tf(s[ni][e]);
            }
        }
        __syncwarp();

        // O += P @ V
#pragma unroll
        for (int ks = 0; ks < 8; ks++) {
            uint4 af = *(const uint4*)&KPs[(w * 8 + ks) * 128 + pSwz];
#pragma unroll
            for (int ni = 0; ni < 8; ni++) {
                uint2 bf = *(const uint2*)&Vs[(ni * 8 + ks) * 64 + (kSwz ^ (8 * (ni & 3)))];
                mma_tf32(o[ni], (const uint32_t*)&af, (const uint32_t*)&bf);
            }
        }
        __syncthreads();   // before next iter overwrites KPs/Vs
    }

    // Finalize and write to g_y in ORIGINAL token order
    const float i0 = 1.0f / l0;
    const float i1 = 1.0f / l1;
    const int lq0 = nq0 * T_ + tq0;
    const int lq1 = nq1 * T_ + tq1;
    float* y0 = &g_y[((size_t)b * L_ + lq0) * C_ + h * D_];
    float* y1 = &g_y[((size_t)b * L_ + lq1) * C_ + h * D_];
#pragma unroll
    for (int ni = 0; ni < 8; ni++) {
        const int col = ni * 8 + c * 2;
        *(float2*)&y0[col] = make_float2(o[ni][0] * i0, o[ni][1] * i0);
        *(float2*)&y1[col] = make_float2(o[ni][2] * i1, o[ni][3] * i1);
    }
}

extern "C" void kernel_launch(void* const* d_in, const int* in_sizes, int n_in,
                              void* d_out, int out_size) {
    const float* x  = (const float*)d_in[0];
    const float* Wq = (const float*)d_in[1];
    const float* Wk = (const float*)d_in[2];
    const float* Wv = (const float*)d_in[3];
    const float* Wo = (const float*)d_in[4];
    const float* bt = (const float*)d_in[5];
    const float* bp = (const float*)d_in[6];
    float* out = (float*)d_out;

    gemm_tc<1><<<dim3(12, 96), 128>>>(x, Wq, Wk, Wv, nullptr);
    attn_tc<<<dim3(L_ / 64, B_ * Hh), 128>>>(bt, bp);
    gemm_tc<0><<<dim3(4, 96), 128>>>(nullptr, Wo, nullptr, nullptr, out);
}